// round 3
// baseline (speedup 1.0000x reference)
#include <cuda_runtime.h>
#include <cuda_bf16.h>
#include <cstdint>
#include <cstddef>

// ===================== problem constants =====================
static constexpr int C_    = 512;
static constexpr int HW_   = 784;            // 28*28
static constexpr int B_    = 64;
static constexpr int MTOT  = B_ * HW_;       // 50176 = 392 * 128
static constexpr int BM    = 128;
static constexpr int BN    = 128;
static constexpr int BK    = 64;             // k-chunk (one 128B swizzle row)
static constexpr int NCHUNK = C_ / BK;       // 8
static constexpr int MTILES = MTOT / BM;     // 392
static constexpr int MT    = 4;              // m-tiles per CTA (392 = 98*4)

// smem layout
static constexpr uint32_t OFF_PARAMS = 0;                       // 4 x 128 floats
static constexpr uint32_t OFF_A      = 2048;                    // 2 stages x 16KB
static constexpr uint32_t TILE_B     = 16384;                   // 128 rows x 128B
static constexpr uint32_t OFF_EPI    = OFF_A + 2 * TILE_B;      // 34816, 128x33 floats
static constexpr uint32_t OFF_B      = 51712;                   // 8 chunks x 16KB
static constexpr uint32_t SMEM_BYTES = OFF_B + NCHUNK * TILE_B; // 182784
static_assert(OFF_EPI + 128 * 33 * 4 <= OFF_B, "epi fits");
static_assert(SMEM_BYTES <= 227 * 1024, "smem");

// ===================== device scratch =====================
__device__ __nv_bfloat16 g_A[(size_t)MTOT * C_];   // sign(x+rb)  [m][c]
__device__ __nv_bfloat16 g_W[(size_t)C_ * C_];     // sign(W)     [o][c]
__device__ float g_alpha[C_];
__device__ float g_cs[C_];

// ===================== helpers =====================
#define DEV_INLINE __device__ __forceinline__

DEV_INLINE uint32_t smem_u32(const void* p) {
    uint32_t a;
    asm("{ .reg .u64 t; cvta.to.shared.u64 t, %1; cvt.u32.u64 %0, t; }" : "=r"(a) : "l"(p));
    return a;
}

DEV_INLINE void cp_async16(uint32_t dst, const void* src) {
    asm volatile("cp.async.cg.shared.global [%0], [%1], 16;"
                 :: "r"(dst), "l"(__cvta_generic_to_global(src)) : "memory");
}
DEV_INLINE void cp_commit() { asm volatile("cp.async.commit_group;" ::: "memory"); }
template <int N>
DEV_INLINE void cp_wait() { asm volatile("cp.async.wait_group %0;" :: "n"(N) : "memory"); }

DEV_INLINE void ldmatrix_x4(uint32_t* r, uint32_t addr) {
    asm volatile("ldmatrix.sync.aligned.m8n8.x4.shared.b16 {%0,%1,%2,%3}, [%4];"
                 : "=r"(r[0]), "=r"(r[1]), "=r"(r[2]), "=r"(r[3]) : "r"(addr));
}

DEV_INLINE void mma_16816(float* c, const uint32_t* a, const uint32_t* b) {
    asm volatile(
        "mma.sync.aligned.m16n8k16.row.col.f32.bf16.bf16.f32 "
        "{%0,%1,%2,%3},{%4,%5,%6,%7},{%8,%9},{%0,%1,%2,%3};"
        : "+f"(c[0]), "+f"(c[1]), "+f"(c[2]), "+f"(c[3])
        : "r"(a[0]), "r"(a[1]), "r"(a[2]), "r"(a[3]), "r"(b[0]), "r"(b[1]));
}

// swizzled 16B-group offset inside a 128x128B tile
DEV_INLINE uint32_t sw_off(int row, int g) {
    return (uint32_t)(row * 128 + (((g ^ (row & 7))) << 4));
}

// ===================== kernel 1: fold constants + binarize W =====================
__global__ void lb_prep_kernel(const float* __restrict__ W, const float* __restrict__ gamma,
                               const float* __restrict__ beta, const float* __restrict__ mean,
                               const float* __restrict__ var, const float* __restrict__ shift) {
    int o = blockIdx.x;
    int t = threadIdx.x;   // 128
    float s = 0.f;
    for (int c = t; c < C_; c += 128) {
        float w = W[o * C_ + c];
        s += fabsf(w);
        g_W[(size_t)o * C_ + c] = __float2bfloat16(w >= 0.f ? 1.f : -1.f);
    }
    __shared__ float red[128];
    red[t] = s;
    __syncthreads();
    for (int k = 64; k > 0; k >>= 1) {
        if (t < k) red[t] += red[t + k];
        __syncthreads();
    }
    if (t == 0) {
        float scale = red[0] * (1.f / 512.f);
        float rstd  = rsqrtf(var[o] + 1e-5f);
        g_alpha[o] = gamma[o] * rstd * scale;
        g_cs[o]    = beta[o] - gamma[o] * mean[o] * rstd - shift[o];
    }
}

// ===================== kernel 2: sign(x+rb), NCHW -> A[m][c] bf16 =====================
__global__ void lb_signcast_kernel(const float* __restrict__ x, const float* __restrict__ rb) {
    __shared__ __nv_bfloat16 tile[32][33];
    int b  = blockIdx.z;
    int c0 = blockIdx.y * 32;
    int h0 = blockIdx.x * 32;
    int tx = threadIdx.x, ty = threadIdx.y;
#pragma unroll
    for (int j = 0; j < 32; j += 8) {
        int c = c0 + ty + j;
        int hw = h0 + tx;
        float v = 1.f;
        if (hw < HW_) v = x[((size_t)b * C_ + c) * HW_ + hw] + rb[c];
        tile[ty + j][tx] = __float2bfloat16(v >= 0.f ? 1.f : -1.f);
    }
    __syncthreads();
#pragma unroll
    for (int j = 0; j < 32; j += 8) {
        int hw = h0 + ty + j;
        if (hw < HW_) {
            size_t m = (size_t)b * HW_ + hw;
            g_A[m * C_ + c0 + tx] = tile[tx][ty + j];
        }
    }
}

// ===================== kernel 3: mma.sync GEMM + fused epilogue =====================
DEV_INLINE void load_a_chunk(uint32_t sb, int mt, int kc, int stage, int tid) {
    const __nv_bfloat16* src = g_A + (size_t)mt * BM * C_ + kc * BK;
    uint32_t dst = sb + OFF_A + stage * TILE_B;
#pragma unroll
    for (int i = tid; i < 1024; i += 256) {
        int row = i >> 3, g = i & 7;
        cp_async16(dst + sw_off(row, g), src + (size_t)row * C_ + g * 8);
    }
}

__global__ __launch_bounds__(256, 1)
void lb_gemm_kernel(const float* __restrict__ x, float* __restrict__ out,
                    const float* __restrict__ pr_slope, const float* __restrict__ pr_bias) {
    extern __shared__ char smem[];
    const uint32_t sb = smem_u32(smem);
    const int tid = threadIdx.x, lane = tid & 31, w = tid >> 5;
    const int n0  = blockIdx.x * BN;
    const int mt0 = blockIdx.y * MT;

    float* sp = (float*)(smem + OFF_PARAMS);   // [alpha|cs|slope|prb] x 128
    if (tid < 128) {
        sp[tid]       = g_alpha[n0 + tid];
        sp[128 + tid] = g_cs[n0 + tid];
        sp[256 + tid] = pr_slope[n0 + tid];
        sp[384 + tid] = pr_bias[n0 + tid];
    }

    // ---- full B tile: 128 n-rows x 512 k (8 chunks), once per CTA ----
    for (int i = tid; i < 8192; i += 256) {
        int kc = i >> 10, row = (i >> 3) & 127, g = i & 7;
        cp_async16(sb + OFF_B + kc * TILE_B + sw_off(row, g),
                   g_W + (size_t)(n0 + row) * C_ + kc * BK + g * 8);
    }
    cp_commit();
    // ---- A chunk 0 ----
    load_a_chunk(sb, mt0, 0, 0, tid);
    cp_commit();

    const int m_off = (w & 1) * 64, n_off = (w >> 1) * 32;
    const int ra      = lane & 15;          // A ldmatrix row (within m-frag)
    const int ka_half = lane >> 4;          // A k-half select
    const int rb_     = (lane & 7) + ((lane >> 4) << 3);  // B ldmatrix row
    const int kb_half = (lane >> 3) & 1;    // B k-half select

    for (int it = 0; it < MT; it++) {
        const int q0 = it * NCHUNK;
        float acc[4][4][4];
#pragma unroll
        for (int mf = 0; mf < 4; mf++)
#pragma unroll
            for (int nf = 0; nf < 4; nf++)
#pragma unroll
                for (int e = 0; e < 4; e++) acc[mf][nf][e] = 0.f;

        for (int kc = 0; kc < NCHUNK; kc++) {
            const int q = q0 + kc;
            if (q + 1 < MT * NCHUNK) {
                load_a_chunk(sb, mt0 + (q + 1) / NCHUNK, (q + 1) % NCHUNK, (q + 1) & 1, tid);
                cp_commit();
                cp_wait<1>();
            } else {
                cp_wait<0>();
            }
            __syncthreads();

            const uint32_t Ab = sb + OFF_A + (q & 1) * TILE_B;
            const uint32_t Bb = sb + OFF_B + kc * TILE_B;
#pragma unroll
            for (int ks = 0; ks < 4; ks++) {
                uint32_t afr[4][4];
#pragma unroll
                for (int mf = 0; mf < 4; mf++) {
                    int row = m_off + mf * 16 + ra;
                    ldmatrix_x4(afr[mf], Ab + sw_off(row, ks * 2 + ka_half));
                }
                uint32_t bfr[2][4];
#pragma unroll
                for (int p = 0; p < 2; p++) {
                    int row = n_off + p * 16 + rb_;
                    ldmatrix_x4(bfr[p], Bb + sw_off(row, ks * 2 + kb_half));
                }
#pragma unroll
                for (int mf = 0; mf < 4; mf++)
#pragma unroll
                    for (int nf = 0; nf < 4; nf++)
                        mma_16816(acc[mf][nf], afr[mf], &bfr[nf >> 1][(nf & 1) * 2]);
            }
            __syncthreads();
        }

        // ---- epilogue: reorder via smem, coalesced NCHW float4 stores ----
        const int mbase = (mt0 + it) * BM;
        float* epi = (float*)(smem + OFF_EPI);   // [128][33]
#pragma unroll 1
        for (int nc = 0; nc < 4; nc++) {
            if ((w >> 1) == nc) {
#pragma unroll
                for (int mf = 0; mf < 4; mf++)
#pragma unroll
                    for (int nf = 0; nf < 4; nf++) {
                        int r = m_off + mf * 16 + (lane >> 2);
                        int c = nf * 8 + (lane & 3) * 2;
                        epi[r * 33 + c]           = acc[mf][nf][0];
                        epi[r * 33 + c + 1]       = acc[mf][nf][1];
                        epi[(r + 8) * 33 + c]     = acc[mf][nf][2];
                        epi[(r + 8) * 33 + c + 1] = acc[mf][nf][3];
                    }
            }
            __syncthreads();
            {
                const int nl = tid >> 3, ms = tid & 7;
                const int n = n0 + nc * 32 + nl;
                const float al = sp[nc * 32 + nl];
                const float c0 = sp[128 + nc * 32 + nl];
                const float sl = sp[256 + nc * 32 + nl];
                const float pb = sp[384 + nc * 32 + nl];
                const int m = mbase + ms * 16;              // 784 % 16 == 0: no b-crossing
                const int bb = m / HW_, hw = m % HW_;
                const size_t base = ((size_t)bb * C_ + n) * HW_ + hw;
#pragma unroll
                for (int j = 0; j < 4; j++) {
                    float4 xv = *(const float4*)(x + base + j * 4);
                    float4 o;
                    float d0 = epi[(ms * 16 + j * 4 + 0) * 33 + nl];
                    float d1 = epi[(ms * 16 + j * 4 + 1) * 33 + nl];
                    float d2 = epi[(ms * 16 + j * 4 + 2) * 33 + nl];
                    float d3 = epi[(ms * 16 + j * 4 + 3) * 33 + nl];
                    float t0 = al * d0 + c0 + xv.x;
                    float t1 = al * d1 + c0 + xv.y;
                    float t2 = al * d2 + c0 + xv.z;
                    float t3 = al * d3 + c0 + xv.w;
                    o.x = (t0 > 0.f ? t0 : sl * t0) + pb;
                    o.y = (t1 > 0.f ? t1 : sl * t1) + pb;
                    o.z = (t2 > 0.f ? t2 : sl * t2) + pb;
                    o.w = (t3 > 0.f ? t3 : sl * t3) + pb;
                    *(float4*)(out + base + j * 4) = o;
                }
            }
            __syncthreads();
        }
    }
}

// ===================== launch =====================
extern "C" void kernel_launch(void* const* d_in, const int* in_sizes, int n_in,
                              void* d_out, int out_size) {
    const float* x     = (const float*)d_in[0];
    const float* rb    = (const float*)d_in[1];
    const float* W     = (const float*)d_in[2];
    const float* gamma = (const float*)d_in[3];
    const float* beta  = (const float*)d_in[4];
    const float* mean  = (const float*)d_in[5];
    const float* var   = (const float*)d_in[6];
    const float* slope = (const float*)d_in[7];
    const float* shift = (const float*)d_in[8];
    const float* prb   = (const float*)d_in[9];
    float* out = (float*)d_out;

    lb_prep_kernel<<<C_, 128>>>(W, gamma, beta, mean, var, shift);
    lb_signcast_kernel<<<dim3((HW_ + 31) / 32, C_ / 32, B_), dim3(32, 8)>>>(x, rb);

    cudaFuncSetAttribute(lb_gemm_kernel, cudaFuncAttributeMaxDynamicSharedMemorySize, SMEM_BYTES);
    lb_gemm_kernel<<<dim3(C_ / BN, MTILES / MT), 256, SMEM_BYTES>>>(x, out, slope, prb);
}

// round 4
// speedup vs baseline: 1.1248x; 1.1248x over previous
#include <cuda_runtime.h>
#include <cuda_bf16.h>
#include <cstdint>
#include <cstddef>

// ===================== problem constants =====================
static constexpr int C_    = 512;
static constexpr int HW_   = 784;            // 28*28
static constexpr int B_    = 64;
static constexpr int MTOT  = B_ * HW_;       // 50176 = 392 * 128
static constexpr int BM    = 128;
static constexpr int BN    = 128;
static constexpr int BKB   = 128;            // k-chunk in BYTES (fp8 => 128 k-elems)
static constexpr int NCHUNK = C_ / BKB;      // 4
static constexpr int MTILES = MTOT / BM;     // 392
static constexpr int MT    = 2;              // m-tiles per CTA
static constexpr int QTOT  = MT * NCHUNK;    // 8 chunks per CTA

// fp8 e4m3 encodings of +1 / -1
static constexpr uint8_t FP8_P1 = 0x38;
static constexpr uint8_t FP8_M1 = 0xB8;

// smem layout
static constexpr uint32_t OFF_PARAMS = 0;                        // 4 x 128 floats = 2048
static constexpr uint32_t OFF_EPI    = 2048;                     // 128 x 33 floats = 16896
static constexpr uint32_t TILE_SZ    = 16384;                    // 128 rows x 128B
static constexpr uint32_t OFF_A      = 19456;                    // 4 stages
static constexpr uint32_t OFF_B      = OFF_A + 4 * TILE_SZ;      // 84992, 4 chunks
static constexpr uint32_t SMEM_BYTES = OFF_B + NCHUNK * TILE_SZ; // 150528
static_assert(SMEM_BYTES <= 227 * 1024, "smem");

// ===================== device scratch =====================
__device__ uint8_t g_A[(size_t)MTOT * C_];   // sign(x+rb) as e4m3, [m][c]
__device__ uint8_t g_W[(size_t)C_ * C_];     // sign(W)    as e4m3, [o][c]
__device__ float g_alpha[C_];
__device__ float g_cs[C_];

// ===================== helpers =====================
#define DEV_INLINE __device__ __forceinline__

DEV_INLINE uint32_t smem_u32(const void* p) {
    uint32_t a;
    asm("{ .reg .u64 t; cvta.to.shared.u64 t, %1; cvt.u32.u64 %0, t; }" : "=r"(a) : "l"(p));
    return a;
}

DEV_INLINE void cp_async16(uint32_t dst, const void* src) {
    asm volatile("cp.async.cg.shared.global [%0], [%1], 16;"
                 :: "r"(dst), "l"(__cvta_generic_to_global(src)) : "memory");
}
DEV_INLINE void cp_commit() { asm volatile("cp.async.commit_group;" ::: "memory"); }
template <int N>
DEV_INLINE void cp_wait() { asm volatile("cp.async.wait_group %0;" :: "n"(N) : "memory"); }

DEV_INLINE void ldmatrix_x4(uint32_t* r, uint32_t addr) {
    asm volatile("ldmatrix.sync.aligned.m8n8.x4.shared.b16 {%0,%1,%2,%3}, [%4];"
                 : "=r"(r[0]), "=r"(r[1]), "=r"(r[2]), "=r"(r[3]) : "r"(addr));
}

// fp8 e4m3 MMA, fp32 accum. k=32.
DEV_INLINE void mma_fp8(float* c, const uint32_t* a, const uint32_t* b) {
    asm volatile(
        "mma.sync.aligned.m16n8k32.row.col.f32.e4m3.e4m3.f32 "
        "{%0,%1,%2,%3},{%4,%5,%6,%7},{%8,%9},{%0,%1,%2,%3};"
        : "+f"(c[0]), "+f"(c[1]), "+f"(c[2]), "+f"(c[3])
        : "r"(a[0]), "r"(a[1]), "r"(a[2]), "r"(a[3]), "r"(b[0]), "r"(b[1]));
}

// swizzled 16B-group offset inside a 128x128B tile
DEV_INLINE uint32_t sw_off(int row, int g) {
    return (uint32_t)(row * 128 + (((g ^ (row & 7))) << 4));
}

// ===================== kernel 1: fold constants + binarize W (warp per row) ==========
__global__ void lb_prep_kernel(const float* __restrict__ W, const float* __restrict__ gamma,
                               const float* __restrict__ beta, const float* __restrict__ mean,
                               const float* __restrict__ var, const float* __restrict__ shift) {
    int warp = threadIdx.x >> 5, lane = threadIdx.x & 31;
    int o = blockIdx.x * 8 + warp;
    const float4* Wr = (const float4*)(W + (size_t)o * C_);
    float s = 0.f;
#pragma unroll
    for (int i = 0; i < 4; i++) {
        float4 f = Wr[i * 32 + lane];
        s += fabsf(f.x) + fabsf(f.y) + fabsf(f.z) + fabsf(f.w);
        uchar4 u;
        u.x = f.x >= 0.f ? FP8_P1 : FP8_M1;
        u.y = f.y >= 0.f ? FP8_P1 : FP8_M1;
        u.z = f.z >= 0.f ? FP8_P1 : FP8_M1;
        u.w = f.w >= 0.f ? FP8_P1 : FP8_M1;
        *(uchar4*)(g_W + (size_t)o * C_ + (i * 32 + lane) * 4) = u;
    }
#pragma unroll
    for (int k = 16; k > 0; k >>= 1) s += __shfl_xor_sync(0xFFFFFFFFu, s, k);
    if (lane == 0) {
        float scale = s * (1.f / 512.f);
        float rstd  = rsqrtf(var[o] + 1e-5f);
        g_alpha[o] = gamma[o] * rstd * scale;
        g_cs[o]    = beta[o] - gamma[o] * mean[o] * rstd - shift[o];
    }
}

// ===================== kernel 2: sign(x+rb), NCHW -> A[m][c] e4m3 ====================
// block (32,8), tile = 128 channels x 32 hw
__global__ void lb_signcast_kernel(const float* __restrict__ x, const float* __restrict__ rb) {
    __shared__ uint8_t tile[128][33];
    int b  = blockIdx.z;
    int c0 = blockIdx.y * 128;
    int h0 = blockIdx.x * 32;
    int tx = threadIdx.x, ty = threadIdx.y;
#pragma unroll
    for (int j = 0; j < 16; j++) {
        int cl = ty + j * 8;
        int c  = c0 + cl;
        int hw = h0 + tx;
        float v = 1.f;
        if (hw < HW_) v = x[((size_t)b * C_ + c) * HW_ + hw] + rb[c];
        tile[cl][tx] = v >= 0.f ? FP8_P1 : FP8_M1;
    }
    __syncthreads();
#pragma unroll
    for (int j = 0; j < 4; j++) {
        int hwl = ty + j * 8;
        int hw  = h0 + hwl;
        if (hw < HW_) {
            size_t m = (size_t)b * HW_ + hw;
            uchar4 u;
            u.x = tile[4 * tx + 0][hwl];
            u.y = tile[4 * tx + 1][hwl];
            u.z = tile[4 * tx + 2][hwl];
            u.w = tile[4 * tx + 3][hwl];
            *(uchar4*)(g_A + m * C_ + c0 + 4 * tx) = u;
        }
    }
}

// ===================== kernel 3: fp8 mma GEMM + fused epilogue =====================
DEV_INLINE void load_a_chunk(uint32_t sb, int q, int mt0, int tid) {
    const int mt = mt0 + (q >> 2), kc = q & 3;
    const uint8_t* src = g_A + (size_t)mt * BM * C_ + kc * BKB;
    uint32_t dst = sb + OFF_A + (q & 3) * TILE_SZ;
#pragma unroll
    for (int i = tid; i < 1024; i += 256) {
        int row = i >> 3, g = i & 7;
        cp_async16(dst + sw_off(row, g), src + (size_t)row * C_ + g * 16);
    }
}

__global__ __launch_bounds__(256, 1)
void lb_gemm_kernel(const float* __restrict__ x, float* __restrict__ out,
                    const float* __restrict__ pr_slope, const float* __restrict__ pr_bias) {
    extern __shared__ char smem[];
    const uint32_t sb = smem_u32(smem);
    const int tid = threadIdx.x, lane = tid & 31, w = tid >> 5;
    const int n0  = blockIdx.x * BN;
    const int mt0 = blockIdx.y * MT;

    float* sp = (float*)(smem + OFF_PARAMS);
    if (tid < 128) {
        sp[tid]       = g_alpha[n0 + tid];
        sp[128 + tid] = g_cs[n0 + tid];
        sp[256 + tid] = pr_slope[n0 + tid];
        sp[384 + tid] = pr_bias[n0 + tid];
    }

    // ---- B tile: 128 n-rows x 512 k-bytes (4 chunks), once per CTA ----  [group 0]
    for (int i = tid; i < 4096; i += 256) {
        int kc = i >> 10, row = (i >> 3) & 127, g = i & 7;
        cp_async16(sb + OFF_B + kc * TILE_SZ + sw_off(row, g),
                   g_W + (size_t)(n0 + row) * C_ + kc * BKB + g * 16);
    }
    cp_commit();
    // ---- prologue: A chunks 0..2 ----
    load_a_chunk(sb, 0, mt0, tid); cp_commit();
    load_a_chunk(sb, 1, mt0, tid); cp_commit();
    load_a_chunk(sb, 2, mt0, tid); cp_commit();

    const int m_off = (w & 1) * 64, n_off = (w >> 1) * 32;
    const int ra      = lane & 15;
    const int ka_half = lane >> 4;
    const int rb_     = (lane & 7) + ((lane >> 4) << 3);
    const int kb_half = (lane >> 3) & 1;

    float acc[4][4][4];
#pragma unroll
    for (int mf = 0; mf < 4; mf++)
#pragma unroll
        for (int nf = 0; nf < 4; nf++)
#pragma unroll
            for (int e = 0; e < 4; e++) acc[mf][nf][e] = 0.f;

#pragma unroll 1
    for (int q = 0; q < QTOT; q++) {
        cp_wait<2>();
        __syncthreads();
        // prefetch q+3 into stage (q+3)&3 == (q-1)&3 (drained by the sync above)
        if (q + 3 < QTOT) load_a_chunk(sb, q + 3, mt0, tid);
        cp_commit();   // empty group when q+3 >= QTOT keeps wait<2> semantics exact

        const uint32_t Ab = sb + OFF_A + (q & 3) * TILE_SZ;
        const uint32_t Bb = sb + OFF_B + (q & 3) * TILE_SZ;
#pragma unroll
        for (int ks = 0; ks < 4; ks++) {
            uint32_t afr[4][4];
#pragma unroll
            for (int mf = 0; mf < 4; mf++) {
                int row = m_off + mf * 16 + ra;
                ldmatrix_x4(afr[mf], Ab + sw_off(row, ks * 2 + ka_half));
            }
            uint32_t bfr[2][4];
#pragma unroll
            for (int p = 0; p < 2; p++) {
                int row = n_off + p * 16 + rb_;
                ldmatrix_x4(bfr[p], Bb + sw_off(row, ks * 2 + kb_half));
            }
#pragma unroll
            for (int mf = 0; mf < 4; mf++)
#pragma unroll
                for (int nf = 0; nf < 4; nf++)
                    mma_fp8(acc[mf][nf], afr[mf], &bfr[nf >> 1][(nf & 1) * 2]);
        }

        if ((q & 3) == 3) {
            // ---- epilogue for m-tile (q>>2) ----
            __syncthreads();   // all warps done reading this stage before epi smem reuse? (epi separate) – orders acc/epi phases
            const int mbase = (mt0 + (q >> 2)) * BM;
            float* epi = (float*)(smem + OFF_EPI);   // [128][33]
#pragma unroll 1
            for (int nc = 0; nc < 4; nc++) {
                if ((w >> 1) == nc) {
#pragma unroll
                    for (int mf = 0; mf < 4; mf++)
#pragma unroll
                        for (int nf = 0; nf < 4; nf++) {
                            int r = m_off + mf * 16 + (lane >> 2);
                            int c = nf * 8 + (lane & 3) * 2;
                            epi[r * 33 + c]           = acc[mf][nf][0];
                            epi[r * 33 + c + 1]       = acc[mf][nf][1];
                            epi[(r + 8) * 33 + c]     = acc[mf][nf][2];
                            epi[(r + 8) * 33 + c + 1] = acc[mf][nf][3];
                        }
                }
                __syncthreads();
                {
                    const int nl = tid >> 3, ms = tid & 7;
                    const int n = n0 + nc * 32 + nl;
                    const float al = sp[nc * 32 + nl];
                    const float c0v = sp[128 + nc * 32 + nl];
                    const float sl = sp[256 + nc * 32 + nl];
                    const float pb = sp[384 + nc * 32 + nl];
                    const int m = mbase + ms * 16;          // 784 % 16 == 0
                    const int bb = m / HW_, hw = m % HW_;
                    const size_t base = ((size_t)bb * C_ + n) * HW_ + hw;
#pragma unroll
                    for (int j = 0; j < 4; j++) {
                        float4 xv = *(const float4*)(x + base + j * 4);
                        float d0 = epi[(ms * 16 + j * 4 + 0) * 33 + nl];
                        float d1 = epi[(ms * 16 + j * 4 + 1) * 33 + nl];
                        float d2 = epi[(ms * 16 + j * 4 + 2) * 33 + nl];
                        float d3 = epi[(ms * 16 + j * 4 + 3) * 33 + nl];
                        float t0 = al * d0 + c0v + xv.x;
                        float t1 = al * d1 + c0v + xv.y;
                        float t2 = al * d2 + c0v + xv.z;
                        float t3 = al * d3 + c0v + xv.w;
                        float4 o;
                        o.x = (t0 > 0.f ? t0 : sl * t0) + pb;
                        o.y = (t1 > 0.f ? t1 : sl * t1) + pb;
                        o.z = (t2 > 0.f ? t2 : sl * t2) + pb;
                        o.w = (t3 > 0.f ? t3 : sl * t3) + pb;
                        *(float4*)(out + base + j * 4) = o;
                    }
                }
                __syncthreads();
            }
            if (q + 1 < QTOT) {
#pragma unroll
                for (int mf = 0; mf < 4; mf++)
#pragma unroll
                    for (int nf = 0; nf < 4; nf++)
#pragma unroll
                        for (int e = 0; e < 4; e++) acc[mf][nf][e] = 0.f;
            }
        }
    }
}

// ===================== launch =====================
extern "C" void kernel_launch(void* const* d_in, const int* in_sizes, int n_in,
                              void* d_out, int out_size) {
    const float* x     = (const float*)d_in[0];
    const float* rb    = (const float*)d_in[1];
    const float* W     = (const float*)d_in[2];
    const float* gamma = (const float*)d_in[3];
    const float* beta  = (const float*)d_in[4];
    const float* mean  = (const float*)d_in[5];
    const float* var   = (const float*)d_in[6];
    const float* slope = (const float*)d_in[7];
    const float* shift = (const float*)d_in[8];
    const float* prb   = (const float*)d_in[9];
    float* out = (float*)d_out;

    lb_prep_kernel<<<C_ / 8, 256>>>(W, gamma, beta, mean, var, shift);
    lb_signcast_kernel<<<dim3((HW_ + 31) / 32, C_ / 128, B_), dim3(32, 8)>>>(x, rb);

    cudaFuncSetAttribute(lb_gemm_kernel, cudaFuncAttributeMaxDynamicSharedMemorySize, SMEM_BYTES);
    lb_gemm_kernel<<<dim3(C_ / BN, MTILES / MT), 256, SMEM_BYTES>>>(x, out, slope, prb);
}